// round 8
// baseline (speedup 1.0000x reference)
#include <cuda_runtime.h>
#include <cuda_bf16.h>

// CovarianceResidualError, fused persistent kernel, mode-W (1 CTA per SM):
//   a_i = graph_emb[i,0];  ACC_j = sum_i e_ij*a_i;  SE_j = sum_i e_ij;  SA = sum_i a_i
//   out = -sum_j |ACC_j - SA*SE_j/N|
//
// 148 CTAs x 1024 threads: exactly one CTA per SM (B300 microarch: multi-CTA
// per-SM occupancy causes up to 2x cross-CTA L1tex-queue finish spread; 1-CTA
// "mode-W" spread is ~1.0). Each CTA streams ~886 rows.
// Grid barrier; blocks 0..127 reduce 2 columns each; ticket block finalizes.

#define NROWS 131072
#define OCOLS 256
#define DCOLS 128
#define NCTA  148
#define NT    1024
#define CHUNK 128
#define NREDB 128                          // reducer blocks, 2 columns each
#define COLV4 (NCTA / 2)                   // 74 float4 per column

__device__ float2 g_pT[OCOLS * NCTA];      // [col][cta] -> (acc, se)
__device__ float  g_psa[NCTA];
__device__ float  g_colA[OCOLS];
__device__ float  g_colS[OCOLS];
__device__ volatile unsigned int g_c1 = 0; // phase-1 completion counter
__device__ unsigned int g_c2 = 0;          // phase-2 ticket

__global__ void __launch_bounds__(NT, 1)
cov_fused_kernel(const float* __restrict__ ge, const float4* __restrict__ err4,
                 float* __restrict__ out)
{
    __shared__ float a_sh[CHUNK];
    __shared__ float red[16 * OCOLS];      // 16 KB phase-reduction scratch
    __shared__ unsigned int s_ticket;

    const int tid = threadIdx.x;
    const int tx  = tid & 63;              // column group: columns 4*tx .. 4*tx+3
    const int ty  = tid >> 6;              // row phase 0..15
    const int bid = blockIdx.x;

    // Balanced row range for this CTA (885 or 886 rows)
    const int r0 = (int)(((long long)bid * NROWS) / NCTA);
    const int r1 = (int)(((long long)(bid + 1) * NROWS) / NCTA);

    // ================= Phase 1: streaming partials =================
    float4 acc = make_float4(0.f, 0.f, 0.f, 0.f);
    float4 se  = make_float4(0.f, 0.f, 0.f, 0.f);
    float  suma = 0.f;

    float a_next = 0.f;
    if (tid < CHUNK && r0 + tid < r1)
        a_next = ge[(size_t)(r0 + tid) * DCOLS];

    for (int base = r0; base < r1; base += CHUNK) {
        const int cn = min(CHUNK, r1 - base);
        __syncthreads();
        if (tid < CHUNK) { a_sh[tid] = a_next; suma += a_next; }
        __syncthreads();
        {
            const int nb = base + CHUNK;
            if (tid < CHUNK && nb + tid < r1)
                a_next = ge[(size_t)(nb + tid) * DCOLS];
            else
                a_next = 0.f;
        }

        #pragma unroll 8
        for (int r = ty; r < cn; r += 16) {
            const float4 e = err4[(size_t)(base + r) * (OCOLS / 4) + tx];
            const float  a = a_sh[r];
            acc.x = fmaf(e.x, a, acc.x); acc.y = fmaf(e.y, a, acc.y);
            acc.z = fmaf(e.z, a, acc.z); acc.w = fmaf(e.w, a, acc.w);
            se.x += e.x; se.y += e.y; se.z += e.z; se.w += e.w;
        }
    }

    // Reduce the 16 row phases (deterministic fixed order, via shared)
    __syncthreads();
    red[ty * OCOLS + 4 * tx + 0] = acc.x;
    red[ty * OCOLS + 4 * tx + 1] = acc.y;
    red[ty * OCOLS + 4 * tx + 2] = acc.z;
    red[ty * OCOLS + 4 * tx + 3] = acc.w;
    __syncthreads();
    float accTot = 0.f;
    if (tid < OCOLS) {
        #pragma unroll
        for (int p = 0; p < 16; ++p) accTot += red[p * OCOLS + tid];
    }
    __syncthreads();
    red[ty * OCOLS + 4 * tx + 0] = se.x;
    red[ty * OCOLS + 4 * tx + 1] = se.y;
    red[ty * OCOLS + 4 * tx + 2] = se.z;
    red[ty * OCOLS + 4 * tx + 3] = se.w;
    __syncthreads();
    if (tid < OCOLS) {
        float seTot = 0.f;
        #pragma unroll
        for (int p = 0; p < 16; ++p) seTot += red[p * OCOLS + tid];
        g_pT[(size_t)tid * NCTA + bid] = make_float2(accTot, seTot);
    }

    // Block partial of SA: fixed-shape tree over the 128 a-loader threads
    __syncthreads();
    if (tid < CHUNK) red[tid] = suma;
    __syncthreads();
    #pragma unroll
    for (int st = 64; st > 0; st >>= 1) {
        if (tid < st) red[tid] += red[tid + st];
        __syncthreads();
    }
    if (tid == 0) {
        g_psa[bid] = red[0];
        __threadfence();
        atomicAdd((unsigned int*)&g_c1, 1u);
    }

    if (bid >= NREDB) return;

    // ================= grid barrier (spin with backoff) =================
    if (tid == 0) {
        while (g_c1 != NCTA) __nanosleep(32);
    }
    __syncthreads();
    __threadfence();

    // ================= Phase 2: 2 columns per block, 1 warp per column ======
    {
        const int w = tid >> 5;
        const int t = tid & 31;
        if (w < 2) {
            const int c = bid * 2 + w;
            const float4* p4 = (const float4*)g_pT;
            float a = 0.f, s = 0.f;
            for (int k = t; k < COLV4; k += 32) {
                const float4 v = p4[(size_t)c * COLV4 + k];
                a += v.x + v.z;            // two (acc,se) pairs per float4
                s += v.y + v.w;
            }
            #pragma unroll
            for (int off = 16; off > 0; off >>= 1) {
                a += __shfl_down_sync(0xffffffffu, a, off);
                s += __shfl_down_sync(0xffffffffu, s, off);
            }
            if (t == 0) {
                g_colA[c] = a;
                g_colS[c] = s;
            }
        }
    }
    __syncthreads();
    if (tid == 0) {
        __threadfence();
        s_ticket = atomicAdd(&g_c2, 1u);
    }
    __syncthreads();

    // ================= Phase 3: last block does final scalar =================
    if (s_ticket == NREDB - 1) {
        __threadfence();
        // SA over 148 block partials (fixed-shape 256-wide tree, zero-padded)
        if (tid < 256) red[tid] = (tid < NCTA) ? g_psa[tid] : 0.f;
        __syncthreads();
        #pragma unroll
        for (int st = 128; st > 0; st >>= 1) {
            if (tid < st) red[tid] += red[tid + st];
            __syncthreads();
        }
        const float k = red[0] * (1.0f / (float)NROWS);
        __syncthreads();

        if (tid < 256) red[tid] = fabsf(g_colA[tid] - k * g_colS[tid]);
        __syncthreads();
        #pragma unroll
        for (int st = 128; st > 0; st >>= 1) {
            if (tid < st) red[tid] += red[tid + st];
            __syncthreads();
        }
        if (tid == 0) {
            out[0] = -red[0];
            g_c2 = 0;                      // reset for next graph replay
            *(unsigned int*)&g_c1 = 0;
            __threadfence();
        }
    }
}

extern "C" void kernel_launch(void* const* d_in, const int* in_sizes, int n_in,
                              void* d_out, int out_size)
{
    const float* ge  = nullptr;   // graph_emb (N x 128)
    const float* err = nullptr;   // errors    (N x 256)
    for (int i = 0; i < n_in; ++i) {
        if (in_sizes[i] == NROWS * DCOLS) ge  = (const float*)d_in[i];
        else if (in_sizes[i] == NROWS * OCOLS) err = (const float*)d_in[i];
    }

    cov_fused_kernel<<<NCTA, NT>>>(ge, (const float4*)err, (float*)d_out);
}

// round 9
// speedup vs baseline: 1.1914x; 1.1914x over previous
#include <cuda_runtime.h>
#include <cuda_bf16.h>

// CovarianceResidualError, two kernels (fusion's spin-barrier polling storm
// throttled L2 during the stream; two launches measured faster):
//   a_i = graph_emb[i,0];  ACC_j = sum_i e_ij*a_i;  SE_j = sum_i e_ij;  SA = sum_i a_i
//   out = -sum_j |ACC_j - SA*SE_j/N|
//
// K1: 512 blocks x 256 threads (proven ~24us @ ~5.8TB/s), __ldcs streaming
//     loads, partials written TRANSPOSED as float2(acc,se) at g_pT[col*NB+bid].
// K2: 256 blocks, block c reads its column as 256 contiguous float4 (one per
//     thread, 1MB fully in flight); ticket-elected last block does SA + final.

#define NROWS 131072
#define OCOLS 256
#define DCOLS 128
#define NB 512
#define ROWS_PER_BLK (NROWS / NB)          // 256
#define CHUNK 64
#define NCHUNK (ROWS_PER_BLK / CHUNK)      // 4

__device__ float2 g_pT[OCOLS * NB];        // [col][block] -> (acc, se)
__device__ float  g_psa[NB];
__device__ float  g_colA[OCOLS];
__device__ float  g_colS[OCOLS];
__device__ unsigned int g_c2 = 0;          // K2 ticket

__global__ void __launch_bounds__(256, 4)
cov_partial_kernel(const float* __restrict__ ge, const float4* __restrict__ err4)
{
    __shared__ float a_sh[CHUNK];
    __shared__ float red[4 * OCOLS];

    const int tid  = threadIdx.x;
    const int tx   = tid & 63;     // column group: columns 4*tx .. 4*tx+3
    const int ty   = tid >> 6;     // row phase 0..3
    const int bid  = blockIdx.x;
    const int row0 = bid * ROWS_PER_BLK;

    float4 acc = make_float4(0.f, 0.f, 0.f, 0.f);
    float4 se  = make_float4(0.f, 0.f, 0.f, 0.f);
    float  suma = 0.f;

    float a_next = 0.f;
    if (tid < CHUNK)
        a_next = __ldcs(&ge[(size_t)(row0 + tid) * DCOLS]);

    for (int c = 0; c < NCHUNK; ++c) {
        const int base = row0 + c * CHUNK;
        __syncthreads();
        if (tid < CHUNK) { a_sh[tid] = a_next; suma += a_next; }
        __syncthreads();
        if (tid < CHUNK && (c + 1) < NCHUNK)
            a_next = __ldcs(&ge[(size_t)(base + CHUNK + tid) * DCOLS]);

        #pragma unroll
        for (int r = ty; r < CHUNK; r += 4) {
            const float4 e = __ldcs(&err4[(size_t)(base + r) * (OCOLS / 4) + tx]);
            const float  a = a_sh[r];
            acc.x = fmaf(e.x, a, acc.x); acc.y = fmaf(e.y, a, acc.y);
            acc.z = fmaf(e.z, a, acc.z); acc.w = fmaf(e.w, a, acc.w);
            se.x += e.x; se.y += e.y; se.z += e.z; se.w += e.w;
        }
    }

    // Reduce the 4 row phases (deterministic, via shared), pack (acc,se)
    __syncthreads();
    red[ty * OCOLS + 4 * tx + 0] = acc.x;
    red[ty * OCOLS + 4 * tx + 1] = acc.y;
    red[ty * OCOLS + 4 * tx + 2] = acc.z;
    red[ty * OCOLS + 4 * tx + 3] = acc.w;
    __syncthreads();
    const float accTot =
        red[tid] + red[OCOLS + tid] + red[2 * OCOLS + tid] + red[3 * OCOLS + tid];
    __syncthreads();
    red[ty * OCOLS + 4 * tx + 0] = se.x;
    red[ty * OCOLS + 4 * tx + 1] = se.y;
    red[ty * OCOLS + 4 * tx + 2] = se.z;
    red[ty * OCOLS + 4 * tx + 3] = se.w;
    __syncthreads();
    const float seTot =
        red[tid] + red[OCOLS + tid] + red[2 * OCOLS + tid] + red[3 * OCOLS + tid];

    // Transposed partial store: column 'tid', block 'bid'
    g_pT[(size_t)tid * NB + bid] = make_float2(accTot, seTot);

    // Block partial of SA (fixed order over 64 chunk-sums)
    __syncthreads();
    if (tid < CHUNK) red[tid] = suma;
    __syncthreads();
    if (tid == 0) {
        float s = 0.f;
        #pragma unroll
        for (int i = 0; i < CHUNK; ++i) s += red[i];
        g_psa[bid] = s;
    }
}

__global__ void __launch_bounds__(256, 4)
cov_reduce_kernel(float* __restrict__ out)
{
    __shared__ float shA[OCOLS];
    __shared__ float shS[OCOLS];
    __shared__ unsigned int s_ticket;

    const int tid = threadIdx.x;
    const int c   = blockIdx.x;

    // Column c = 512 contiguous float2 = 256 float4; one float4 per thread.
    const float4 v = ((const float4*)g_pT)[(size_t)c * (NB / 2) + tid];
    shA[tid] = v.x + v.z;          // two (acc,se) pairs per float4
    shS[tid] = v.y + v.w;
    __syncthreads();
    #pragma unroll
    for (int st = 128; st > 0; st >>= 1) {
        if (tid < st) {
            shA[tid] += shA[tid + st];
            shS[tid] += shS[tid + st];
        }
        __syncthreads();
    }
    if (tid == 0) {
        g_colA[c] = shA[0];
        g_colS[c] = shS[0];
        __threadfence();
        s_ticket = atomicAdd(&g_c2, 1u);
    }
    __syncthreads();

    // Last-arriving block: SA + deterministic final |.| sum
    if (s_ticket == OCOLS - 1) {
        __threadfence();
        shA[tid] = g_psa[tid] + g_psa[tid + 256];
        __syncthreads();
        #pragma unroll
        for (int st = 128; st > 0; st >>= 1) {
            if (tid < st) shA[tid] += shA[tid + st];
            __syncthreads();
        }
        const float k = shA[0] * (1.0f / (float)NROWS);
        __syncthreads();

        shA[tid] = fabsf(g_colA[tid] - k * g_colS[tid]);
        __syncthreads();
        #pragma unroll
        for (int st = 128; st > 0; st >>= 1) {
            if (tid < st) shA[tid] += shA[tid + st];
            __syncthreads();
        }
        if (tid == 0) {
            out[0] = -shA[0];
            g_c2 = 0;              // reset for next graph replay
            __threadfence();
        }
    }
}

extern "C" void kernel_launch(void* const* d_in, const int* in_sizes, int n_in,
                              void* d_out, int out_size)
{
    const float* ge  = nullptr;   // graph_emb (N x 128)
    const float* err = nullptr;   // errors    (N x 256)
    for (int i = 0; i < n_in; ++i) {
        if (in_sizes[i] == NROWS * DCOLS) ge  = (const float*)d_in[i];
        else if (in_sizes[i] == NROWS * OCOLS) err = (const float*)d_in[i];
    }

    cov_partial_kernel<<<NB, 256>>>(ge, (const float4*)err);
    cov_reduce_kernel<<<OCOLS, 256>>>((float*)d_out);
}

// round 10
// speedup vs baseline: 1.2144x; 1.0193x over previous
#include <cuda_runtime.h>
#include <cuda_bf16.h>

// CovarianceResidualError, single kernel, deterministic int64-atomic reduction:
//   a_i = graph_emb[i,0];  ACC_j = sum_i e_ij*a_i;  SE_j = sum_i e_ij;  SA = sum_i a_i
//   out = -sum_j |ACC_j - SA*SE_j/N|
//
// Every prior variant paid a ~8us dependent-reduction tail (invariant to
// parallelism). Here per-block fp32 partials are quantized to int64 (scale
// 2^40) and accumulated with u64 atomics -- integer adds are exactly
// associative, so the result is bit-deterministic regardless of arrival
// order. The last-finishing block (ticket) finalizes from L2 and re-zeros
// the accumulators for the next graph replay.

#define NROWS 131072
#define OCOLS 256
#define DCOLS 128
#define NB 512
#define ROWS_PER_BLK (NROWS / NB)          // 256
#define CHUNK 64
#define NCHUNK (ROWS_PER_BLK / CHUNK)      // 4

#define SCALE   1099511627776.0f           // 2^40
#define INVSCALE (1.0 / 1099511627776.0)   // 2^-40 (double)

__device__ unsigned long long g_iacc[OCOLS];   // int64 accumulators (2's compl)
__device__ unsigned long long g_ise [OCOLS];
__device__ unsigned long long g_isa;
__device__ unsigned int g_ct = 0;              // completion ticket

__device__ __forceinline__ unsigned long long q40(float v) {
    return (unsigned long long)(long long)llrintf(v * SCALE);
}

__global__ void __launch_bounds__(256, 4)
cov_kernel(const float* __restrict__ ge, const float4* __restrict__ err4,
           float* __restrict__ out)
{
    __shared__ float a_sh[CHUNK];
    __shared__ float red[4 * OCOLS];
    __shared__ unsigned int s_ticket;

    const int tid  = threadIdx.x;
    const int tx   = tid & 63;     // column group: columns 4*tx .. 4*tx+3
    const int ty   = tid >> 6;     // row phase 0..3
    const int bid  = blockIdx.x;
    const int row0 = bid * ROWS_PER_BLK;

    // ================= streaming partials (proven loop) =================
    float4 acc = make_float4(0.f, 0.f, 0.f, 0.f);
    float4 se  = make_float4(0.f, 0.f, 0.f, 0.f);
    float  suma = 0.f;

    float a_next = 0.f;
    if (tid < CHUNK)
        a_next = __ldcs(&ge[(size_t)(row0 + tid) * DCOLS]);

    for (int c = 0; c < NCHUNK; ++c) {
        const int base = row0 + c * CHUNK;
        __syncthreads();
        if (tid < CHUNK) { a_sh[tid] = a_next; suma += a_next; }
        __syncthreads();
        if (tid < CHUNK && (c + 1) < NCHUNK)
            a_next = __ldcs(&ge[(size_t)(base + CHUNK + tid) * DCOLS]);

        #pragma unroll
        for (int r = ty; r < CHUNK; r += 4) {
            const float4 e = __ldcs(&err4[(size_t)(base + r) * (OCOLS / 4) + tx]);
            const float  a = a_sh[r];
            acc.x = fmaf(e.x, a, acc.x); acc.y = fmaf(e.y, a, acc.y);
            acc.z = fmaf(e.z, a, acc.z); acc.w = fmaf(e.w, a, acc.w);
            se.x += e.x; se.y += e.y; se.z += e.z; se.w += e.w;
        }
    }

    // Reduce the 4 row phases (deterministic, via shared)
    __syncthreads();
    red[ty * OCOLS + 4 * tx + 0] = acc.x;
    red[ty * OCOLS + 4 * tx + 1] = acc.y;
    red[ty * OCOLS + 4 * tx + 2] = acc.z;
    red[ty * OCOLS + 4 * tx + 3] = acc.w;
    __syncthreads();
    const float accTot =
        red[tid] + red[OCOLS + tid] + red[2 * OCOLS + tid] + red[3 * OCOLS + tid];
    __syncthreads();
    red[ty * OCOLS + 4 * tx + 0] = se.x;
    red[ty * OCOLS + 4 * tx + 1] = se.y;
    red[ty * OCOLS + 4 * tx + 2] = se.z;
    red[ty * OCOLS + 4 * tx + 3] = se.w;
    __syncthreads();
    const float seTot =
        red[tid] + red[OCOLS + tid] + red[2 * OCOLS + tid] + red[3 * OCOLS + tid];

    // Deterministic global accumulation: integer atomics (order-independent)
    atomicAdd(&g_iacc[tid], q40(accTot));
    atomicAdd(&g_ise [tid], q40(seTot));

    // Block partial of SA (fixed order over 64 chunk-sums)
    __syncthreads();
    if (tid < CHUNK) red[tid] = suma;
    __syncthreads();
    if (tid == 0) {
        float s = 0.f;
        #pragma unroll
        for (int i = 0; i < CHUNK; ++i) s += red[i];
        atomicAdd(&g_isa, q40(s));
        __threadfence();
        s_ticket = atomicAdd(&g_ct, 1u);
    }
    __syncthreads();

    // ================= last-finishing block finalizes =================
    if (s_ticket == NB - 1) {
        __threadfence();
        const double A = (double)(long long)g_iacc[tid] * INVSCALE;
        const double S = (double)(long long)g_ise [tid] * INVSCALE;
        const double k = ((double)(long long)g_isa * INVSCALE) / (double)NROWS;

        red[tid] = (float)fabs(A - k * S);
        __syncthreads();
        #pragma unroll
        for (int st = 128; st > 0; st >>= 1) {
            if (tid < st) red[tid] += red[tid + st];
            __syncthreads();
        }
        if (tid == 0) out[0] = -red[0];

        // Re-zero accumulators for the next graph replay (deterministic state)
        g_iacc[tid] = 0ull;
        g_ise [tid] = 0ull;
        if (tid == 0) { g_isa = 0ull; g_ct = 0u; }
        __threadfence();
    }
}

extern "C" void kernel_launch(void* const* d_in, const int* in_sizes, int n_in,
                              void* d_out, int out_size)
{
    const float* ge  = nullptr;   // graph_emb (N x 128)
    const float* err = nullptr;   // errors    (N x 256)
    for (int i = 0; i < n_in; ++i) {
        if (in_sizes[i] == NROWS * DCOLS) ge  = (const float*)d_in[i];
        else if (in_sizes[i] == NROWS * OCOLS) err = (const float*)d_in[i];
    }

    cov_kernel<<<NB, 256>>>(ge, (const float4*)err, (float*)d_out);
}